// round 5
// baseline (speedup 1.0000x reference)
#include <cuda_runtime.h>
#include <cuda_bf16.h>
#include <math.h>

// Problem constants
constexpr int S = 4;
constexpr int T = 512;
constexpr int B = 16;
constexpr int D = 512;

constexpr int TCHUNK = 16;             // t rows per block
constexpr int NCHUNK = T / TCHUNK;     // 32 chunks per batch
constexpr int NBLOCKS = NCHUNK * B;    // 512 blocks
constexpr int NACC   = 24;             // 16 dots (sp*4+sg) + 4 pred norms + 4 gt norms

using u64 = unsigned long long;

// Deterministic scratch: per-(batch, chunk) partial accumulators.
__device__ float g_part[B][NCHUNK][NACC];
__device__ int   g_done = 0;

__device__ __forceinline__ void fma2(u64& acc, u64 a, u64 b) {
    asm("fma.rn.f32x2 %0, %1, %2, %0;" : "+l"(acc) : "l"(a), "l"(b));
}
__device__ __forceinline__ float unpack_sum(u64 v) {
    float lo, hi;
    asm("mov.b64 {%0, %1}, %2;" : "=f"(lo), "=f"(hi) : "l"(v));
    return lo + hi;
}

// ---------------------------------------------------------------------------
// Fused kernel.
// Phase A (all 512 blocks): streaming Gram reduction for (batch b, 16 t rows).
//   Thread tid owns floats d = {2*tid, 2*tid+1} of every row -> coalesced
//   8B loads; every accumulator update is one packed fma.rn.f32x2.
// Phase B (last block to finish): reduce the 16x32x24 partials, build the
//   4x4 distance matrices, greedy first-occurrence matching, write scalar.
// ---------------------------------------------------------------------------
__global__ __launch_bounds__(256) void minloss_fused(
    const float* __restrict__ preds,   // [S, T, B, D]
    const float* __restrict__ gts,     // [S, B, T, D]
    float* __restrict__ out)
{
    const int b   = blockIdx.y;
    const int c   = blockIdx.x;
    const int t0  = c * TCHUNK;
    const int tid = threadIdx.x;

    // Base pointers (as 8-byte words) per source
    const u64* pp[S];
    const u64* gg[S];
#pragma unroll
    for (int s = 0; s < S; ++s) {
        pp[s] = (const u64*)preds + ((size_t)(s * T + t0) * B + b) * (D / 2) + tid;
        gg[s] = (const u64*)gts   + ((size_t)(s * B + b) * T + t0) * (D / 2) + tid;
    }
    constexpr int PSTRIDE = B * D / 2;   // 4096 words per t
    constexpr int GSTRIDE = D / 2;       // 256 words per t

    u64 acc[NACC];
#pragma unroll
    for (int i = 0; i < NACC; ++i) acc[i] = 0ull;   // bit pattern == (0.f, 0.f)

#pragma unroll 4
    for (int tt = 0; tt < TCHUNK; ++tt) {
        u64 p[4], g[4];
#pragma unroll
        for (int s = 0; s < 4; ++s) {
            p[s] = pp[s][(size_t)tt * PSTRIDE];
            g[s] = gg[s][(size_t)tt * GSTRIDE];
        }
#pragma unroll
        for (int sp = 0; sp < 4; ++sp) {
            fma2(acc[16 + sp], p[sp], p[sp]);        // pred norms
            fma2(acc[20 + sp], g[sp], g[sp]);        // gt norms
#pragma unroll
            for (int sg = 0; sg < 4; ++sg)
                fma2(acc[sp * 4 + sg], p[sp], g[sg]); // dots
        }
    }

    // Unpack + warp reduction
    float vals[NACC];
#pragma unroll
    for (int i = 0; i < NACC; ++i) {
        vals[i] = unpack_sum(acc[i]);
#pragma unroll
        for (int off = 16; off > 0; off >>= 1)
            vals[i] += __shfl_down_sync(0xffffffffu, vals[i], off);
    }

    __shared__ float sacc[8][NACC];
    const int warp = tid >> 5;
    const int lane = tid & 31;
    if (lane == 0) {
#pragma unroll
        for (int i = 0; i < NACC; ++i) sacc[warp][i] = vals[i];
    }
    __syncthreads();

    if (tid < NACC) {
        float a = 0.0f;
#pragma unroll
        for (int w = 0; w < 8; ++w) a += sacc[w][tid];
        g_part[b][c][tid] = a;                       // deterministic overwrite
    }

    // ---- last-block ticket ----
    __threadfence();                                  // make g_part visible GPU-wide
    __syncthreads();
    __shared__ int s_last;
    if (tid == 0) {
        int ticket = atomicAdd(&g_done, 1);
        s_last = (ticket == NBLOCKS - 1);
    }
    __syncthreads();
    if (!s_last) return;

    // =========================== Phase B (last block) ===========================
    __threadfence();                                  // acquire side

    __shared__ float s_final[B][NACC];

    // 8 warps, warp w reduces batches 2w and 2w+1 over the 32 chunks.
    // Lanes 0..23 each own one accumulator index.
#pragma unroll
    for (int k = 0; k < 2; ++k) {
        const int bb = warp * 2 + k;
        if (lane < NACC) {
            float a = 0.0f;
#pragma unroll
            for (int cc = 0; cc < NCHUNK; ++cc)
                a += __ldcg(&g_part[bb][cc][lane]);   // L2, bypass stale L1
            s_final[bb][lane] = a;
        }
    }
    __syncthreads();

    __shared__ float batch_total[B];

    // 16 threads: one greedy matching per batch.
    if (tid < B) {
        const float* a = s_final[tid];
        float dist[16];
#pragma unroll
        for (int sp = 0; sp < 4; ++sp)
#pragma unroll
            for (int sg = 0; sg < 4; ++sg) {
                float d2 = a[16 + sp] + a[20 + sg] - 2.0f * a[sp * 4 + sg];
                dist[sp * 4 + sg] = sqrtf(fmaxf(d2, 0.0f));
            }

        const float INF = __int_as_float(0x7f800000);
        float total = 0.0f;
#pragma unroll
        for (int it = 0; it < 4; ++it) {
            int   m    = 0;
            float best = dist[0];
#pragma unroll
            for (int k = 1; k < 16; ++k)
                if (dist[k] < best) { best = dist[k]; m = k; }  // first occurrence
            total += best;
            const int r = m >> 2, cc = m & 3;
#pragma unroll
            for (int k = 0; k < 4; ++k) {
                dist[r * 4 + k]  = INF;
                dist[k * 4 + cc] = INF;
            }
        }
        batch_total[tid] = total;
    }
    __syncthreads();

    if (tid == 0) {
        float s = 0.0f;
#pragma unroll
        for (int bb = 0; bb < B; ++bb) s += batch_total[bb];
        out[0] = s;
        g_done = 0;                                   // reset for next graph replay
    }
}

extern "C" void kernel_launch(void* const* d_in, const int* in_sizes, int n_in,
                              void* d_out, int out_size)
{
    const float* preds = (const float*)d_in[0];  // [4, 512, 16, 512]
    const float* gts   = (const float*)d_in[1];  // [4, 16, 512, 512]
    float* out = (float*)d_out;

    dim3 grid(NCHUNK, B);                        // (32, 16) = 512 blocks
    minloss_fused<<<grid, 256>>>(preds, gts, out);
}

// round 6
// speedup vs baseline: 1.2193x; 1.2193x over previous
#include <cuda_runtime.h>
#include <cuda_bf16.h>
#include <math.h>

// Problem constants
constexpr int S = 4;
constexpr int T = 512;
constexpr int B = 16;
constexpr int D = 512;

constexpr int RPAIRS = T / 2;          // 256 t-row pairs per batch
constexpr int CPB    = 18;             // blocks (chunks) per batch
constexpr int NBLOCKS = CPB * B;       // 288 = ~148 SMs * occ 2, one wave
constexpr int NACC   = 24;             // 16 dots (sp*4+sg) + 4 pred norms + 4 gt norms

using u64 = unsigned long long;

// Deterministic scratch: per-(batch, block-slot) partial accumulators.
__device__ float g_part[B][CPB][NACC];
__device__ int   g_done = 0;

__device__ __forceinline__ void fma2(u64& acc, u64 a, u64 b) {
    asm("fma.rn.f32x2 %0, %1, %2, %0;" : "+l"(acc) : "l"(a), "l"(b));
}
__device__ __forceinline__ float unpack_sum(u64 v) {
    float lo, hi;
    asm("mov.b64 {%0, %1}, %2;" : "=f"(lo), "=f"(hi) : "l"(v));
    return lo + hi;
}

// ---------------------------------------------------------------------------
// Fused single-wave kernel.
// Block (cx, b): batch b, row pairs rp = cx, cx+18, ... (< 256).
// Thread layout: lane128 = tid & 127 spans D via float4 (128 * 4 = 512);
// tid >> 7 selects the row within the pair. All loads are LDG.128, fully
// coalesced (128 threads * 16B = 2KB contiguous per row).
// Accumulators stay in registers across the entire stride loop; one partial
// write per block. Last block reduces 288 partials + greedy matching.
// ---------------------------------------------------------------------------
__global__ __launch_bounds__(256, 2) void minloss_fused(
    const float* __restrict__ preds,   // [S, T, B, D]
    const float* __restrict__ gts,     // [S, B, T, D]
    float* __restrict__ out)
{
    const int b    = blockIdx.y;
    const int cx   = blockIdx.x;
    const int tid  = threadIdx.x;
    const int lane128 = tid & 127;
    const int trow    = tid >> 7;      // 0 or 1: row within the pair

    const ulonglong2* pv = (const ulonglong2*)preds;  // 16B vectors, D/4=128 per row
    const ulonglong2* gv = (const ulonglong2*)gts;

    u64 acc[NACC];
#pragma unroll
    for (int i = 0; i < NACC; ++i) acc[i] = 0ull;     // == (0.f, 0.f)

    for (int rp = cx; rp < RPAIRS; rp += CPB) {
        const int t = 2 * rp + trow;
        ulonglong2 p[4], g[4];
#pragma unroll
        for (int s = 0; s < 4; ++s) {
            p[s] = pv[((size_t)(s * T + t) * B + b) * 128 + lane128];
            g[s] = gv[((size_t)(s * B + b) * T + t) * 128 + lane128];
        }
#pragma unroll
        for (int sp = 0; sp < 4; ++sp) {
            fma2(acc[16 + sp], p[sp].x, p[sp].x);     // pred norm
            fma2(acc[16 + sp], p[sp].y, p[sp].y);
            fma2(acc[20 + sp], g[sp].x, g[sp].x);     // gt norm
            fma2(acc[20 + sp], g[sp].y, g[sp].y);
#pragma unroll
            for (int sg = 0; sg < 4; ++sg) {
                fma2(acc[sp * 4 + sg], p[sp].x, g[sg].x);
                fma2(acc[sp * 4 + sg], p[sp].y, g[sg].y);
            }
        }
    }

    // Unpack + warp reduction
    float vals[NACC];
#pragma unroll
    for (int i = 0; i < NACC; ++i) {
        vals[i] = unpack_sum(acc[i]);
#pragma unroll
        for (int off = 16; off > 0; off >>= 1)
            vals[i] += __shfl_down_sync(0xffffffffu, vals[i], off);
    }

    __shared__ float sacc[8][NACC];
    const int warp = tid >> 5;
    const int lane = tid & 31;
    if (lane == 0) {
#pragma unroll
        for (int i = 0; i < NACC; ++i) sacc[warp][i] = vals[i];
    }
    __syncthreads();

    if (tid < NACC) {
        float a = 0.0f;
#pragma unroll
        for (int w = 0; w < 8; ++w) a += sacc[w][tid];
        g_part[b][cx][tid] = a;                       // deterministic overwrite
    }

    // ---- last-block ticket ----
    __threadfence();
    __syncthreads();
    __shared__ int s_last;
    if (tid == 0) {
        int ticket = atomicAdd(&g_done, 1);
        s_last = (ticket == NBLOCKS - 1);
    }
    __syncthreads();
    if (!s_last) return;

    // =========================== Phase B (last block) ===========================
    __threadfence();                                  // acquire

    __shared__ float s_final[B][NACC];

    // 8 warps; warp w reduces batches 2w and 2w+1. Lanes 0..23 own one acc idx.
#pragma unroll
    for (int k = 0; k < 2; ++k) {
        const int bb = warp * 2 + k;
        if (lane < NACC) {
            float a = 0.0f;
#pragma unroll
            for (int cc = 0; cc < CPB; ++cc)
                a += __ldcg(&g_part[bb][cc][lane]);   // L2, bypass stale L1
            s_final[bb][lane] = a;
        }
    }
    __syncthreads();

    __shared__ float batch_total[B];

    // 16 threads: one greedy matching per batch (first-occurrence argmin order).
    if (tid < B) {
        const float* a = s_final[tid];
        float dist[16];
#pragma unroll
        for (int sp = 0; sp < 4; ++sp)
#pragma unroll
            for (int sg = 0; sg < 4; ++sg) {
                float d2 = a[16 + sp] + a[20 + sg] - 2.0f * a[sp * 4 + sg];
                dist[sp * 4 + sg] = sqrtf(fmaxf(d2, 0.0f));
            }

        const float INF = __int_as_float(0x7f800000);
        float total = 0.0f;
#pragma unroll
        for (int it = 0; it < 4; ++it) {
            int   m    = 0;
            float best = dist[0];
#pragma unroll
            for (int k = 1; k < 16; ++k)
                if (dist[k] < best) { best = dist[k]; m = k; }
            total += best;
            const int r = m >> 2, cc = m & 3;
#pragma unroll
            for (int k = 0; k < 4; ++k) {
                dist[r * 4 + k]  = INF;
                dist[k * 4 + cc] = INF;
            }
        }
        batch_total[tid] = total;
    }
    __syncthreads();

    if (tid == 0) {
        float s = 0.0f;
#pragma unroll
        for (int bb = 0; bb < B; ++bb) s += batch_total[bb];
        out[0] = s;
        g_done = 0;                                   // reset for next graph replay
    }
}

extern "C" void kernel_launch(void* const* d_in, const int* in_sizes, int n_in,
                              void* d_out, int out_size)
{
    const float* preds = (const float*)d_in[0];  // [4, 512, 16, 512]
    const float* gts   = (const float*)d_in[1];  // [4, 16, 512, 512]
    float* out = (float*)d_out;

    dim3 grid(CPB, B);                           // (18, 16) = 288 blocks, one wave
    minloss_fused<<<grid, 256>>>(preds, gts, out);
}